// round 10
// baseline (speedup 1.0000x reference)
#include <cuda_runtime.h>
#include <stdint.h>

// BloomEmbedding: out[n, h*32 + j] = tables[h, hash(ids[n], 42+h), j]
// ids: [819200] int32, tables: [4, 1000000, 32] f32, out: [819200, 128] f32
//
// R10: R9 staggered dual-batch (8 in-flight gathers/thread, all issued before
// the first store's scoreboard wait) + forced 32-reg budget via
// __launch_bounds__(256, 8) to lift occupancy 63% -> ~80%, testing the
// last untried (high-MLP x high-occ) cell of the bandwidth matrix.
// Phased by table (blockIdx.y): active footprint 71.5MB < 126MB L2 keeps
// hash-repeat traffic in L2 (traffic is at the ~691MB structural floor).

#define TABLE_SIZE 1000000u
#define SEED 42u
#define BATCH 4
#define IDS_PER_THREAD 8   // two staggered batches of 4

__device__ __forceinline__ uint32_t hash_id(uint32_t id, uint32_t seed) {
    uint32_t x = id + seed;
    x ^= x >> 16;
    x *= 0x7FEB352Du;
    x ^= x >> 15;
    x *= 0x846CA68Bu;
    x ^= x >> 16;
    return x % TABLE_SIZE;
}

__global__ void __launch_bounds__(256, 8)
bloom_embedding_kernel(const int* __restrict__ ids,
                       const float4* __restrict__ tables,
                       float4* __restrict__ out,
                       int n_ids) {
    const int h = blockIdx.y;                    // table phase 0..3
    const uint32_t seed = SEED + (uint32_t)h;
    const uint32_t base = (uint32_t)h * TABLE_SIZE;

    int t = blockIdx.x * blockDim.x + threadIdx.x;
    int j = t & 7;                               // float4 within the 32-float sub-row
    int g = t >> 3;                              // id-group index
    int n0 = g * IDS_PER_THREAD;                 // first id of this group (8-aligned)
    if (n0 >= n_ids) return;

    const uint32_t col = (uint32_t)(h * 8 + j);  // out float4 column for (h, j)

    if (n0 + IDS_PER_THREAD <= n_ids) {
        // ---- batch A: ids n0..n0+3 ----
        int4 idA = __ldg((const int4*)(ids + n0));
        uint32_t srcA[BATCH];
        srcA[0] = (base + hash_id((uint32_t)idA.x, seed)) * 8u + (uint32_t)j;
        srcA[1] = (base + hash_id((uint32_t)idA.y, seed)) * 8u + (uint32_t)j;
        srcA[2] = (base + hash_id((uint32_t)idA.z, seed)) * 8u + (uint32_t)j;
        srcA[3] = (base + hash_id((uint32_t)idA.w, seed)) * 8u + (uint32_t)j;
        float4 vA[BATCH];
        #pragma unroll
        for (int k = 0; k < BATCH; k++) vA[k] = __ldcg(tables + srcA[k]);

        // ---- batch B: ids n0+4..n0+7 (hash while A is in flight) ----
        int4 idB = __ldg((const int4*)(ids + n0 + 4));
        uint32_t srcB[BATCH];
        srcB[0] = (base + hash_id((uint32_t)idB.x, seed)) * 8u + (uint32_t)j;
        srcB[1] = (base + hash_id((uint32_t)idB.y, seed)) * 8u + (uint32_t)j;
        srcB[2] = (base + hash_id((uint32_t)idB.z, seed)) * 8u + (uint32_t)j;
        srcB[3] = (base + hash_id((uint32_t)idB.w, seed)) * 8u + (uint32_t)j;
        float4 vB[BATCH];
        #pragma unroll
        for (int k = 0; k < BATCH; k++) vB[k] = __ldcg(tables + srcB[k]);

        // ---- drain A, then B ----
        #pragma unroll
        for (int k = 0; k < BATCH; k++)
            __stcs(out + (size_t)(n0 + k) * 32u + col, vA[k]);
        #pragma unroll
        for (int k = 0; k < BATCH; k++)
            __stcs(out + (size_t)(n0 + 4 + k) * 32u + col, vB[k]);
    } else {
        for (int k = 0; k < IDS_PER_THREAD && n0 + k < n_ids; k++) {
            uint32_t id  = (uint32_t)__ldg(ids + n0 + k);
            uint32_t idx = hash_id(id, seed);
            float4 v = __ldcg(tables + (size_t)(base + idx) * 8u + (size_t)j);
            __stcs(out + (size_t)(n0 + k) * 32u + col, v);
        }
    }
}

extern "C" void kernel_launch(void* const* d_in, const int* in_sizes, int n_in,
                              void* d_out, int out_size) {
    const int*    ids    = (const int*)d_in[0];
    const float4* tables = (const float4*)d_in[1];
    float4*       out    = (float4*)d_out;

    int n_ids = in_sizes[0];                     // 819200
    // per phase: one thread per (8-id group, j): n_ids/8 groups * 8 threads
    long long per_phase = ((long long)n_ids + IDS_PER_THREAD - 1) / IDS_PER_THREAD * 8;
    int threads = 256;
    dim3 grid((unsigned)((per_phase + threads - 1) / threads), 4, 1);
    bloom_embedding_kernel<<<grid, threads>>>(ids, tables, out, n_ids);
}

// round 11
// speedup vs baseline: 1.0688x; 1.0688x over previous
#include <cuda_runtime.h>
#include <stdint.h>

// BloomEmbedding: out[n, h*32 + j] = tables[h, hash(ids[n], 42+h), j]
// ids: [819200] int32, tables: [4, 1000000, 32] f32, out: [819200, 128] f32
//
// FINAL (R9 config, measured best 113.3us kernel / 6.08 TB/s):
//  - Table-phased (blockIdx.y = h, x-fastest dispatch => ~sequential phases):
//    active table footprint 71.5MB < 126MB L2, so intra-table hash-repeat
//    gathers hit L2. Cut DRAM traffic ~750 -> ~691 MB (structural floor:
//    419MB irreducible writes + ~272MB post-capture gather reads).
//  - Staggered dual 4-id batches: all 8 independent LDG.128 gathers issue
//    before the first store's scoreboard wait (MLP well past the Little's-law
//    knee measured at R3).
//  - __ldcg gathers (L2-only), __stcs full-128B-line stores (evict-first).
//  - Natural 38-reg allocation; forcing 32 regs (R10) spills and regresses.

#define TABLE_SIZE 1000000u
#define SEED 42u
#define BATCH 4
#define IDS_PER_THREAD 8   // two staggered batches of 4

__device__ __forceinline__ uint32_t hash_id(uint32_t id, uint32_t seed) {
    uint32_t x = id + seed;
    x ^= x >> 16;
    x *= 0x7FEB352Du;
    x ^= x >> 15;
    x *= 0x846CA68Bu;
    x ^= x >> 16;
    return x % TABLE_SIZE;
}

__global__ void __launch_bounds__(256)
bloom_embedding_kernel(const int* __restrict__ ids,
                       const float4* __restrict__ tables,
                       float4* __restrict__ out,
                       int n_ids) {
    const int h = blockIdx.y;                    // table phase 0..3
    const uint32_t seed = SEED + (uint32_t)h;
    const uint32_t base = (uint32_t)h * TABLE_SIZE;

    int t = blockIdx.x * blockDim.x + threadIdx.x;
    int j = t & 7;                               // float4 within the 32-float sub-row
    int g = t >> 3;                              // id-group index
    int n0 = g * IDS_PER_THREAD;                 // first id of this group (8-aligned)
    if (n0 >= n_ids) return;

    const uint32_t col = (uint32_t)(h * 8 + j);  // out float4 column for (h, j)

    if (n0 + IDS_PER_THREAD <= n_ids) {
        // ---- batch A: ids n0..n0+3 ----
        int4 idA = __ldg((const int4*)(ids + n0));
        uint32_t srcA[BATCH];
        srcA[0] = (base + hash_id((uint32_t)idA.x, seed)) * 8u + (uint32_t)j;
        srcA[1] = (base + hash_id((uint32_t)idA.y, seed)) * 8u + (uint32_t)j;
        srcA[2] = (base + hash_id((uint32_t)idA.z, seed)) * 8u + (uint32_t)j;
        srcA[3] = (base + hash_id((uint32_t)idA.w, seed)) * 8u + (uint32_t)j;
        float4 vA[BATCH];
        #pragma unroll
        for (int k = 0; k < BATCH; k++) vA[k] = __ldcg(tables + srcA[k]);

        // ---- batch B: ids n0+4..n0+7 (hash while A is in flight) ----
        int4 idB = __ldg((const int4*)(ids + n0 + 4));
        uint32_t srcB[BATCH];
        srcB[0] = (base + hash_id((uint32_t)idB.x, seed)) * 8u + (uint32_t)j;
        srcB[1] = (base + hash_id((uint32_t)idB.y, seed)) * 8u + (uint32_t)j;
        srcB[2] = (base + hash_id((uint32_t)idB.z, seed)) * 8u + (uint32_t)j;
        srcB[3] = (base + hash_id((uint32_t)idB.w, seed)) * 8u + (uint32_t)j;
        float4 vB[BATCH];
        #pragma unroll
        for (int k = 0; k < BATCH; k++) vB[k] = __ldcg(tables + srcB[k]);

        // ---- drain A, then B ----
        #pragma unroll
        for (int k = 0; k < BATCH; k++)
            __stcs(out + (size_t)(n0 + k) * 32u + col, vA[k]);
        #pragma unroll
        for (int k = 0; k < BATCH; k++)
            __stcs(out + (size_t)(n0 + 4 + k) * 32u + col, vB[k]);
    } else {
        for (int k = 0; k < IDS_PER_THREAD && n0 + k < n_ids; k++) {
            uint32_t id  = (uint32_t)__ldg(ids + n0 + k);
            uint32_t idx = hash_id(id, seed);
            float4 v = __ldcg(tables + (size_t)(base + idx) * 8u + (size_t)j);
            __stcs(out + (size_t)(n0 + k) * 32u + col, v);
        }
    }
}

extern "C" void kernel_launch(void* const* d_in, const int* in_sizes, int n_in,
                              void* d_out, int out_size) {
    const int*    ids    = (const int*)d_in[0];
    const float4* tables = (const float4*)d_in[1];
    float4*       out    = (float4*)d_out;

    int n_ids = in_sizes[0];                     // 819200
    // per phase: one thread per (8-id group, j): n_ids/8 groups * 8 threads
    long long per_phase = ((long long)n_ids + IDS_PER_THREAD - 1) / IDS_PER_THREAD * 8;
    int threads = 256;
    dim3 grid((unsigned)((per_phase + threads - 1) / threads), 4, 1);
    bloom_embedding_kernel<<<grid, threads>>>(ids, tables, out, n_ids);
}

// round 12
// speedup vs baseline: 1.0898x; 1.0197x over previous
#include <cuda_runtime.h>
#include <stdint.h>

// BloomEmbedding: out[n, h*32 + j] = tables[h, hash(ids[n], 42+h), j]
// ids: [819200] int32, tables: [4, 1000000, 32] f32, out: [819200, 128] f32
//
// FINAL (R9 config, measured best 113.3us kernel / 6.08 TB/s):
//  - Table-phased (blockIdx.y = h, x-fastest dispatch => ~sequential phases):
//    active table footprint 71.5MB < 126MB L2, so intra-table hash-repeat
//    gathers hit L2. Cut DRAM traffic ~750 -> ~691 MB (structural floor:
//    419MB irreducible writes + ~272MB post-capture gather reads).
//  - Staggered dual 4-id batches: all 8 independent LDG.128 gathers issue
//    before the first store's scoreboard wait (MLP well past the Little's-law
//    knee measured at R3).
//  - __ldcg gathers (L2-only), __stcs full-128B-line stores (evict-first).
//  - Natural 38-reg allocation; forcing 32 regs (R10) spills and regresses.

#define TABLE_SIZE 1000000u
#define SEED 42u
#define BATCH 4
#define IDS_PER_THREAD 8   // two staggered batches of 4

__device__ __forceinline__ uint32_t hash_id(uint32_t id, uint32_t seed) {
    uint32_t x = id + seed;
    x ^= x >> 16;
    x *= 0x7FEB352Du;
    x ^= x >> 15;
    x *= 0x846CA68Bu;
    x ^= x >> 16;
    return x % TABLE_SIZE;
}

__global__ void __launch_bounds__(256)
bloom_embedding_kernel(const int* __restrict__ ids,
                       const float4* __restrict__ tables,
                       float4* __restrict__ out,
                       int n_ids) {
    const int h = blockIdx.y;                    // table phase 0..3
    const uint32_t seed = SEED + (uint32_t)h;
    const uint32_t base = (uint32_t)h * TABLE_SIZE;

    int t = blockIdx.x * blockDim.x + threadIdx.x;
    int j = t & 7;                               // float4 within the 32-float sub-row
    int g = t >> 3;                              // id-group index
    int n0 = g * IDS_PER_THREAD;                 // first id of this group (8-aligned)
    if (n0 >= n_ids) return;

    const uint32_t col = (uint32_t)(h * 8 + j);  // out float4 column for (h, j)

    if (n0 + IDS_PER_THREAD <= n_ids) {
        // ---- batch A: ids n0..n0+3 ----
        int4 idA = __ldg((const int4*)(ids + n0));
        uint32_t srcA[BATCH];
        srcA[0] = (base + hash_id((uint32_t)idA.x, seed)) * 8u + (uint32_t)j;
        srcA[1] = (base + hash_id((uint32_t)idA.y, seed)) * 8u + (uint32_t)j;
        srcA[2] = (base + hash_id((uint32_t)idA.z, seed)) * 8u + (uint32_t)j;
        srcA[3] = (base + hash_id((uint32_t)idA.w, seed)) * 8u + (uint32_t)j;
        float4 vA[BATCH];
        #pragma unroll
        for (int k = 0; k < BATCH; k++) vA[k] = __ldcg(tables + srcA[k]);

        // ---- batch B: ids n0+4..n0+7 (hash while A is in flight) ----
        int4 idB = __ldg((const int4*)(ids + n0 + 4));
        uint32_t srcB[BATCH];
        srcB[0] = (base + hash_id((uint32_t)idB.x, seed)) * 8u + (uint32_t)j;
        srcB[1] = (base + hash_id((uint32_t)idB.y, seed)) * 8u + (uint32_t)j;
        srcB[2] = (base + hash_id((uint32_t)idB.z, seed)) * 8u + (uint32_t)j;
        srcB[3] = (base + hash_id((uint32_t)idB.w, seed)) * 8u + (uint32_t)j;
        float4 vB[BATCH];
        #pragma unroll
        for (int k = 0; k < BATCH; k++) vB[k] = __ldcg(tables + srcB[k]);

        // ---- drain A, then B ----
        #pragma unroll
        for (int k = 0; k < BATCH; k++)
            __stcs(out + (size_t)(n0 + k) * 32u + col, vA[k]);
        #pragma unroll
        for (int k = 0; k < BATCH; k++)
            __stcs(out + (size_t)(n0 + 4 + k) * 32u + col, vB[k]);
    } else {
        for (int k = 0; k < IDS_PER_THREAD && n0 + k < n_ids; k++) {
            uint32_t id  = (uint32_t)__ldg(ids + n0 + k);
            uint32_t idx = hash_id(id, seed);
            float4 v = __ldcg(tables + (size_t)(base + idx) * 8u + (size_t)j);
            __stcs(out + (size_t)(n0 + k) * 32u + col, v);
        }
    }
}

extern "C" void kernel_launch(void* const* d_in, const int* in_sizes, int n_in,
                              void* d_out, int out_size) {
    const int*    ids    = (const int*)d_in[0];
    const float4* tables = (const float4*)d_in[1];
    float4*       out    = (float4*)d_out;

    int n_ids = in_sizes[0];                     // 819200
    // per phase: one thread per (8-id group, j): n_ids/8 groups * 8 threads
    long long per_phase = ((long long)n_ids + IDS_PER_THREAD - 1) / IDS_PER_THREAD * 8;
    int threads = 256;
    dim3 grid((unsigned)((per_phase + threads - 1) / threads), 4, 1);
    bloom_embedding_kernel<<<grid, threads>>>(ids, tables, out, n_ids);
}